// round 2
// baseline (speedup 1.0000x reference)
#include <cuda_runtime.h>
#include <cuda_bf16.h>

// Problem shape (fixed by the reference): pred [16,4,512,512] f32, target/ME [16,512,512] i32
#define NUM_CLASSES 4
#define IGNORE_INDEX 4
#define BATCH 16
#define HW 262144            // 512*512 (pixels per batch)
#define NPIX (BATCH * HW)    // 4,194,304
#define NVEC (NPIX / 4)      // 1,048,576 float4-groups
#define GRID 2048
#define TPB 256
// NVEC == GRID * TPB * 2 exactly -> each thread handles 2 groups, no bounds checks

__device__ float2   g_partials[GRID];   // written every run by every block -> no init needed
__device__ unsigned g_ticket = 0;       // self-resetting via atomicInc wrap

__device__ __forceinline__ void pixel_nll(float v0, float v1, float v2, float v3,
                                          int t, int me,
                                          float& acc, float& cnt) {
    float m = fmaxf(fmaxf(v0, v1), fmaxf(v2, v3));
    float s = __expf(v0 - m) + __expf(v1 - m) + __expf(v2 - m) + __expf(v3 - m);
    float lse = m + __logf(s);
    int tc = min(t, NUM_CLASSES - 1);
    float vt = (tc == 0) ? v0 : (tc == 1) ? v1 : (tc == 2) ? v2 : v3;
    float nll = lse - vt;
    float w = (me == 0) ? 1.0f : 0.5f;
    bool valid = (t != IGNORE_INDEX);
    acc += valid ? (w * nll) : 0.0f;
    cnt += valid ? 1.0f : 0.0f;
}

__device__ __forceinline__ void do_group(const float* __restrict__ pred,
                                         const int* __restrict__ target,
                                         const int* __restrict__ me,
                                         int i, float& acc, float& cnt) {
    int p = i << 2;
    int b = p >> 18;                 // p / HW (HW = 2^18)
    int hw = p & (HW - 1);
    size_t base = (size_t)b * (NUM_CLASSES * (size_t)HW) + hw;

    float4 c0 = __ldcs(reinterpret_cast<const float4*>(pred + base));
    float4 c1 = __ldcs(reinterpret_cast<const float4*>(pred + base + HW));
    float4 c2 = __ldcs(reinterpret_cast<const float4*>(pred + base + 2 * (size_t)HW));
    float4 c3 = __ldcs(reinterpret_cast<const float4*>(pred + base + 3 * (size_t)HW));
    int4 tg = __ldcs(reinterpret_cast<const int4*>(target + p));
    int4 mv = __ldcs(reinterpret_cast<const int4*>(me + p));

    pixel_nll(c0.x, c1.x, c2.x, c3.x, tg.x, mv.x, acc, cnt);
    pixel_nll(c0.y, c1.y, c2.y, c3.y, tg.y, mv.y, acc, cnt);
    pixel_nll(c0.z, c1.z, c2.z, c3.z, tg.z, mv.z, acc, cnt);
    pixel_nll(c0.w, c1.w, c2.w, c3.w, tg.w, mv.w, acc, cnt);
}

__global__ void __launch_bounds__(TPB)
ce_fused_kernel(const float* __restrict__ pred,
                const int* __restrict__ target,
                const int* __restrict__ me,
                float* __restrict__ out) {
    float acc = 0.0f, cnt = 0.0f;

    const int tid = blockIdx.x * TPB + threadIdx.x;
    // two statically-offset groups, fully unrolled -> 12 front-batched LDG.128
    do_group(pred, target, me, tid,               acc, cnt);
    do_group(pred, target, me, tid + GRID * TPB,  acc, cnt);

    // warp reduction
    #pragma unroll
    for (int off = 16; off > 0; off >>= 1) {
        acc += __shfl_down_sync(0xFFFFFFFFu, acc, off);
        cnt += __shfl_down_sync(0xFFFFFFFFu, cnt, off);
    }

    // block reduction across 8 warps
    __shared__ float s_acc[8];
    __shared__ float s_cnt[8];
    __shared__ bool  s_last;
    int wid = threadIdx.x >> 5;
    int lid = threadIdx.x & 31;
    if (lid == 0) { s_acc[wid] = acc; s_cnt[wid] = cnt; }
    __syncthreads();
    if (threadIdx.x == 0) {
        float a = 0.0f, c = 0.0f;
        #pragma unroll
        for (int w = 0; w < 8; w++) { a += s_acc[w]; c += s_cnt[w]; }
        g_partials[blockIdx.x] = make_float2(a, c);
        __threadfence();
        unsigned old = atomicInc(&g_ticket, GRID - 1);  // wraps to 0 after last block
        s_last = (old == GRID - 1);
    }
    __syncthreads();

    // last-arriving block reduces all partials and writes the scalar
    if (s_last) {
        double da = 0.0, dc = 0.0;
        #pragma unroll
        for (int k = 0; k < GRID / TPB; k++) {        // 8 partials per thread
            float2 v = g_partials[threadIdx.x + k * TPB];
            da += (double)v.x;
            dc += (double)v.y;
        }
        #pragma unroll
        for (int off = 16; off > 0; off >>= 1) {
            da += __shfl_down_sync(0xFFFFFFFFu, da, off);
            dc += __shfl_down_sync(0xFFFFFFFFu, dc, off);
        }
        __shared__ double d_acc[8];
        __shared__ double d_cnt[8];
        if (lid == 0) { d_acc[wid] = da; d_cnt[wid] = dc; }
        __syncthreads();
        if (threadIdx.x == 0) {
            double fa = 0.0, fc = 0.0;
            #pragma unroll
            for (int w = 0; w < 8; w++) { fa += d_acc[w]; fc += d_cnt[w]; }
            out[0] = (float)(fa / fc);
        }
    }
}

extern "C" void kernel_launch(void* const* d_in, const int* in_sizes, int n_in,
                              void* d_out, int out_size) {
    const float* pred   = (const float*)d_in[0];
    const int*   target = (const int*)d_in[1];
    const int*   me     = (const int*)d_in[2];
    float* out = (float*)d_out;

    ce_fused_kernel<<<GRID, TPB>>>(pred, target, me, out);
}

// round 3
// speedup vs baseline: 1.2314x; 1.2314x over previous
#include <cuda_runtime.h>
#include <cuda_bf16.h>

// Problem shape (fixed by the reference): pred [16,4,512,512] f32, target/ME [16,512,512] i32
#define NUM_CLASSES 4
#define IGNORE_INDEX 4
#define HW 262144            // 512*512 (pixels per batch)
#define NPIX (16 * HW)       // 4,194,304
#define NVEC (NPIX / 4)      // 1,048,576 float4-groups
#define GRID 4096
#define TPB 256
// NVEC == GRID * TPB exactly -> one group per thread, no loop, no bounds checks

__device__ float2   g_partials[GRID];   // written unconditionally every run -> no init needed
__device__ unsigned g_ticket = 0;       // self-resetting via atomicInc wrap

__device__ __forceinline__ void pixel_nll(float v0, float v1, float v2, float v3,
                                          int t, int me,
                                          float& acc, float& cnt) {
    float m = fmaxf(fmaxf(v0, v1), fmaxf(v2, v3));
    float s = __expf(v0 - m) + __expf(v1 - m) + __expf(v2 - m) + __expf(v3 - m);
    float lse = m + __logf(s);
    int tc = min(t, NUM_CLASSES - 1);
    float vt = (tc == 0) ? v0 : (tc == 1) ? v1 : (tc == 2) ? v2 : v3;
    float nll = lse - vt;
    float w = (me == 0) ? 1.0f : 0.5f;
    bool valid = (t != IGNORE_INDEX);
    acc += valid ? (w * nll) : 0.0f;
    cnt += valid ? 1.0f : 0.0f;
}

__global__ void __launch_bounds__(TPB)
ce_fused_kernel(const float* __restrict__ pred,
                const int* __restrict__ target,
                const int* __restrict__ me,
                float* __restrict__ out) {
    float acc = 0.0f, cnt = 0.0f;

    const int i = blockIdx.x * TPB + threadIdx.x;   // group index in [0, NVEC)
    const int p = i << 2;                           // first pixel of this group
    const int b = p >> 18;                          // p / HW  (HW = 2^18)
    const int hw = p & (HW - 1);
    const size_t base = (size_t)b * (NUM_CLASSES * (size_t)HW) + hw;

    float4 c0 = *reinterpret_cast<const float4*>(pred + base);
    float4 c1 = *reinterpret_cast<const float4*>(pred + base + HW);
    float4 c2 = *reinterpret_cast<const float4*>(pred + base + 2 * (size_t)HW);
    float4 c3 = *reinterpret_cast<const float4*>(pred + base + 3 * (size_t)HW);
    int4 tg = *reinterpret_cast<const int4*>(target + p);
    int4 mv = *reinterpret_cast<const int4*>(me + p);

    pixel_nll(c0.x, c1.x, c2.x, c3.x, tg.x, mv.x, acc, cnt);
    pixel_nll(c0.y, c1.y, c2.y, c3.y, tg.y, mv.y, acc, cnt);
    pixel_nll(c0.z, c1.z, c2.z, c3.z, tg.z, mv.z, acc, cnt);
    pixel_nll(c0.w, c1.w, c2.w, c3.w, tg.w, mv.w, acc, cnt);

    // warp reduction
    #pragma unroll
    for (int off = 16; off > 0; off >>= 1) {
        acc += __shfl_down_sync(0xFFFFFFFFu, acc, off);
        cnt += __shfl_down_sync(0xFFFFFFFFu, cnt, off);
    }

    // block reduction across 8 warps
    __shared__ float s_acc[8];
    __shared__ float s_cnt[8];
    __shared__ bool  s_last;
    const int wid = threadIdx.x >> 5;
    const int lid = threadIdx.x & 31;
    if (lid == 0) { s_acc[wid] = acc; s_cnt[wid] = cnt; }
    __syncthreads();
    if (threadIdx.x == 0) {
        float a = 0.0f, c = 0.0f;
        #pragma unroll
        for (int w = 0; w < 8; w++) { a += s_acc[w]; c += s_cnt[w]; }
        g_partials[blockIdx.x] = make_float2(a, c);
        __threadfence();
        unsigned old = atomicInc(&g_ticket, GRID - 1);  // wraps to 0 after last block
        s_last = (old == GRID - 1);
    }
    __syncthreads();

    // last-arriving block reduces all partials and writes the scalar (float is
    // plenty: 4096 values of ~2.5e3 each, tolerance is 1e-3 rel)
    if (s_last) {
        float a = 0.0f, c = 0.0f;
        #pragma unroll
        for (int k = 0; k < GRID / TPB; k++) {          // 16 partials per thread
            float2 v = g_partials[threadIdx.x + k * TPB];
            a += v.x;
            c += v.y;
        }
        #pragma unroll
        for (int off = 16; off > 0; off >>= 1) {
            a += __shfl_down_sync(0xFFFFFFFFu, a, off);
            c += __shfl_down_sync(0xFFFFFFFFu, c, off);
        }
        if (lid == 0) { s_acc[wid] = a; s_cnt[wid] = c; }
        __syncthreads();
        if (threadIdx.x == 0) {
            float fa = 0.0f, fc = 0.0f;
            #pragma unroll
            for (int w = 0; w < 8; w++) { fa += s_acc[w]; fc += s_cnt[w]; }
            out[0] = fa / fc;
        }
    }
}

extern "C" void kernel_launch(void* const* d_in, const int* in_sizes, int n_in,
                              void* d_out, int out_size) {
    const float* pred   = (const float*)d_in[0];
    const int*   target = (const int*)d_in[1];
    const int*   me     = (const int*)d_in[2];
    float* out = (float*)d_out;

    ce_fused_kernel<<<GRID, TPB>>>(pred, target, me, out);
}